// round 1
// baseline (speedup 1.0000x reference)
#include <cuda_runtime.h>

// metadata order: d_in[0]=x (float32, 4*4096*4096), d_in[1]=coeffs (float32, 3),
//                 d_in[2]=importance (float32, 4096). output float32, 67108864 elems.

#define D 4096
#define KEEP 2048
#define N_TOTAL (4 * 4096 * 4096)
#define N4 (N_TOTAL / 4)

// scratch: channel mask as float {0,1}, stored as float4-aligned device global
__device__ float4 g_mask4[D / 4];

// ---------------------------------------------------------------------------
// Kernel 1: compute exact top-k channel mask (reproduces lax.top_k tie-break:
// on equal values, lower index wins).
// ---------------------------------------------------------------------------
__global__ void mask_kernel(const float* __restrict__ imp) {
    __shared__ float s[D];
    for (int j = threadIdx.x; j < D; j += blockDim.x)
        s[j] = imp[j];
    __syncthreads();

    int d = blockIdx.x * blockDim.x + threadIdx.x;  // 32 blocks * 128 threads = 4096
    float v = s[d];
    int rank = 0;
    #pragma unroll 8
    for (int j = 0; j < D; ++j) {
        float w = s[j];
        rank += (w > v) || (w == v && j < d);
    }
    reinterpret_cast<float*>(g_mask4)[d] = (rank < KEEP) ? 1.0f : 0.0f;
}

// ---------------------------------------------------------------------------
// Kernel 2: streaming polynomial. out = mask ? c0*x + c1*x^2 + c2*x^3 : x
// One float4 per thread; mask re-read per vector hits L1/L2 (16 KB array).
// ---------------------------------------------------------------------------
__global__ void __launch_bounds__(256) poly_kernel(
    const float4* __restrict__ x,
    float4* __restrict__ out,
    const float* __restrict__ coeffs)
{
    const float c0 = coeffs[0];
    const float c1 = coeffs[1];
    const float c2 = coeffs[2];

    int i = blockIdx.x * blockDim.x + threadIdx.x;  // 0 .. N4-1
    float4 xv = x[i];
    float4 mv = g_mask4[i & (D / 4 - 1)];           // column within a row of 1024 float4

    // Horner: y = x*(c0 + x*(c1 + x*c2))
    float y0 = xv.x * fmaf(xv.x, fmaf(xv.x, c2, c1), c0);
    float y1 = xv.y * fmaf(xv.y, fmaf(xv.y, c2, c1), c0);
    float y2 = xv.z * fmaf(xv.z, fmaf(xv.z, c2, c1), c0);
    float y3 = xv.w * fmaf(xv.w, fmaf(xv.w, c2, c1), c0);

    float4 ov;
    ov.x = (mv.x != 0.0f) ? y0 : xv.x;
    ov.y = (mv.y != 0.0f) ? y1 : xv.y;
    ov.z = (mv.z != 0.0f) ? y2 : xv.z;
    ov.w = (mv.w != 0.0f) ? y3 : xv.w;
    out[i] = ov;
}

extern "C" void kernel_launch(void* const* d_in, const int* in_sizes, int n_in,
                              void* d_out, int out_size) {
    const float* x      = (const float*)d_in[0];
    const float* coeffs = (const float*)d_in[1];
    const float* imp    = (const float*)d_in[2];
    float* out          = (float*)d_out;

    mask_kernel<<<D / 128, 128>>>(imp);
    poly_kernel<<<N4 / 256, 256>>>((const float4*)x, (float4*)out, coeffs);
}

// round 2
// speedup vs baseline: 1.3031x; 1.3031x over previous
#include <cuda_runtime.h>

// metadata order: d_in[0]=x (float32, 4*4096*4096), d_in[1]=coeffs (float32, 3),
//                 d_in[2]=importance (float32, 4096). output float32, 67108864 elems.

#define D 4096
#define KEEP 2048
#define N_TOTAL (4 * 4096 * 4096)
#define N4 (N_TOTAL / 4)            // 16,777,216 float4
#define VEC_PER_THREAD 4
#define POLY_BLOCK 256
#define POLY_GRID (N4 / (POLY_BLOCK * VEC_PER_THREAD))  // 16384

// scratch: channel mask as float {0,1}, float4-aligned device global
__device__ float4 g_mask4[D / 4];

// ---------------------------------------------------------------------------
// Kernel 1: exact top-k channel mask, one WARP per channel.
// rank(d) = #{j: imp[j] > imp[d]} + #{j < d: imp[j] == imp[d]}  (lax.top_k
// tie-break: lower index wins). Kept iff rank < KEEP.
// ---------------------------------------------------------------------------
__global__ void __launch_bounds__(256) mask_kernel(const float* __restrict__ imp) {
    __shared__ float s[D];
    for (int j = threadIdx.x; j < D; j += blockDim.x)
        s[j] = imp[j];
    __syncthreads();

    const int warp_id = (blockIdx.x * blockDim.x + threadIdx.x) >> 5;  // 0..4095
    const int lane    = threadIdx.x & 31;
    const int d       = warp_id;
    const float v     = s[d];

    int rank = 0;
    #pragma unroll 4
    for (int j = lane; j < D; j += 32) {
        float w = s[j];
        rank += (w > v) || (w == v && j < d);
    }
    // warp reduction
    #pragma unroll
    for (int off = 16; off > 0; off >>= 1)
        rank += __shfl_xor_sync(0xFFFFFFFFu, rank, off);

    if (lane == 0)
        reinterpret_cast<float*>(g_mask4)[d] = (rank < KEEP) ? 1.0f : 0.0f;
}

// ---------------------------------------------------------------------------
// Kernel 2: streaming polynomial. out = mask ? x*(c0 + x*(c1 + x*c2)) : x
// 4 float4 per thread, front-batched streaming loads (L1 bypass), streaming
// stores. Mask (16 KB) stays L2/L1-resident via default cached loads.
// ---------------------------------------------------------------------------
__global__ void __launch_bounds__(POLY_BLOCK) poly_kernel(
    const float4* __restrict__ x,
    float4* __restrict__ out,
    const float* __restrict__ coeffs)
{
    const float c0 = coeffs[0];
    const float c1 = coeffs[1];
    const float c2 = coeffs[2];

    const int base = blockIdx.x * (POLY_BLOCK * VEC_PER_THREAD) + threadIdx.x;

    float4 xv[VEC_PER_THREAD];
    float4 mv[VEC_PER_THREAD];

    // front-batch all loads for max MLP
    #pragma unroll
    for (int k = 0; k < VEC_PER_THREAD; ++k) {
        int i = base + k * POLY_BLOCK;
        xv[k] = __ldcs(&x[i]);                 // stream, don't pollute L1
        mv[k] = __ldg(&g_mask4[i & (D / 4 - 1)]);  // hot 16 KB, keep cached
    }

    #pragma unroll
    for (int k = 0; k < VEC_PER_THREAD; ++k) {
        float4 xk = xv[k];
        float4 mk = mv[k];
        float4 ov;
        ov.x = (mk.x != 0.0f) ? xk.x * fmaf(xk.x, fmaf(xk.x, c2, c1), c0) : xk.x;
        ov.y = (mk.y != 0.0f) ? xk.y * fmaf(xk.y, fmaf(xk.y, c2, c1), c0) : xk.y;
        ov.z = (mk.z != 0.0f) ? xk.z * fmaf(xk.z, fmaf(xk.z, c2, c1), c0) : xk.z;
        ov.w = (mk.w != 0.0f) ? xk.w * fmaf(xk.w, fmaf(xk.w, c2, c1), c0) : xk.w;
        __stcs(&out[base + k * POLY_BLOCK], ov);  // streaming store
    }
}

extern "C" void kernel_launch(void* const* d_in, const int* in_sizes, int n_in,
                              void* d_out, int out_size) {
    const float* x      = (const float*)d_in[0];
    const float* coeffs = (const float*)d_in[1];
    const float* imp    = (const float*)d_in[2];
    float* out          = (float*)d_out;

    mask_kernel<<<(D * 32) / 256, 256>>>(imp);   // 512 blocks, one warp per channel
    poly_kernel<<<POLY_GRID, POLY_BLOCK>>>((const float4*)x, (float4*)out, coeffs);
}

// round 3
// speedup vs baseline: 1.3040x; 1.0007x over previous
#include <cuda_runtime.h>

// metadata order: d_in[0]=x (float32, 4*4096*4096), d_in[1]=coeffs (float32, 3),
//                 d_in[2]=importance (float32, 4096). output float32, 67108864 elems.

#define D 4096
#define KEEP 2048
#define N_TOTAL (4 * 4096 * 4096)
#define N4 (N_TOTAL / 4)            // 16,777,216 float4
#define VEC_PER_THREAD 8
#define POLY_BLOCK 256
#define POLY_GRID (N4 / (POLY_BLOCK * VEC_PER_THREAD))  // 8192

// scratch: channel mask as float {0,1}, float4-aligned device global
__device__ float4 g_mask4[D / 4];

// ---------------------------------------------------------------------------
// Kernel 1: exact top-k channel mask, one WARP per channel.
// rank(d) = #{j: imp[j] > imp[d]} + #{j < d: imp[j] == imp[d]}  (lax.top_k
// tie-break: lower index wins). Kept iff rank < KEEP.
// PDL primary: completion implicitly triggers the dependent poly launch.
// ---------------------------------------------------------------------------
__global__ void __launch_bounds__(256) mask_kernel(const float* __restrict__ imp) {
    __shared__ float s[D];
    for (int j = threadIdx.x; j < D; j += blockDim.x)
        s[j] = imp[j];
    __syncthreads();

    const int warp_id = (blockIdx.x * blockDim.x + threadIdx.x) >> 5;  // 0..4095
    const int lane    = threadIdx.x & 31;
    const int d       = warp_id;
    const float v     = s[d];

    int rank = 0;
    #pragma unroll 8
    for (int j = lane; j < D; j += 32) {
        float w = s[j];
        rank += (w > v) || (w == v && j < d);
    }
    #pragma unroll
    for (int off = 16; off > 0; off >>= 1)
        rank += __shfl_xor_sync(0xFFFFFFFFu, rank, off);

    if (lane == 0)
        reinterpret_cast<float*>(g_mask4)[d] = (rank < KEEP) ? 1.0f : 0.0f;
}

// ---------------------------------------------------------------------------
// Kernel 2: streaming polynomial (PDL secondary).
// Phase A (overlapped with mask_kernel): front-batch 8 streaming float4 loads.
// Phase B (after grid-dependency sync): mask select + Horner + streaming store.
// ---------------------------------------------------------------------------
__global__ void __launch_bounds__(POLY_BLOCK) poly_kernel(
    const float4* __restrict__ x,
    float4* __restrict__ out,
    const float* __restrict__ coeffs)
{
    const int base = blockIdx.x * (POLY_BLOCK * VEC_PER_THREAD) + threadIdx.x;

    float4 xv[VEC_PER_THREAD];
    #pragma unroll
    for (int k = 0; k < VEC_PER_THREAD; ++k)
        xv[k] = __ldcs(&x[base + k * POLY_BLOCK]);   // stream, bypass L1

    // Wait for mask_kernel grid to complete (writes to g_mask4 visible after).
    cudaGridDependencySynchronize();

    const float c0 = coeffs[0];
    const float c1 = coeffs[1];
    const float c2 = coeffs[2];

    #pragma unroll
    for (int k = 0; k < VEC_PER_THREAD; ++k) {
        int i = base + k * POLY_BLOCK;
        float4 mk = __ldg(&g_mask4[i & (D / 4 - 1)]);  // hot 16 KB, L1-resident
        float4 xk = xv[k];
        float4 ov;
        ov.x = (mk.x != 0.0f) ? xk.x * fmaf(xk.x, fmaf(xk.x, c2, c1), c0) : xk.x;
        ov.y = (mk.y != 0.0f) ? xk.y * fmaf(xk.y, fmaf(xk.y, c2, c1), c0) : xk.y;
        ov.z = (mk.z != 0.0f) ? xk.z * fmaf(xk.z, fmaf(xk.z, c2, c1), c0) : xk.z;
        ov.w = (mk.w != 0.0f) ? xk.w * fmaf(xk.w, fmaf(xk.w, c2, c1), c0) : xk.w;
        __stcs(&out[i], ov);                           // streaming store
    }
}

extern "C" void kernel_launch(void* const* d_in, const int* in_sizes, int n_in,
                              void* d_out, int out_size) {
    const float* x      = (const float*)d_in[0];
    const float* coeffs = (const float*)d_in[1];
    const float* imp    = (const float*)d_in[2];
    float* out          = (float*)d_out;

    // Primary: mask kernel (512 blocks, one warp per channel).
    mask_kernel<<<(D * 32) / 256, 256>>>(imp);

    // Secondary: poly kernel with programmatic dependent launch — starts while
    // mask_kernel is still running; cudaGridDependencySynchronize() inside the
    // kernel enforces the ordering before the mask is read.
    cudaLaunchAttribute attrs[1];
    attrs[0].id = cudaLaunchAttributeProgrammaticStreamSerialization;
    attrs[0].val.programmaticStreamSerializationAllowed = 1;

    cudaLaunchConfig_t cfg = {};
    cfg.gridDim  = dim3(POLY_GRID, 1, 1);
    cfg.blockDim = dim3(POLY_BLOCK, 1, 1);
    cfg.dynamicSmemBytes = 0;
    cfg.stream = 0;  // legacy default stream (same one the harness captures)
    cfg.attrs = attrs;
    cfg.numAttrs = 1;

    cudaLaunchKernelEx(&cfg, poly_kernel, (const float4*)x, (float4*)out, coeffs);
}